// round 1
// baseline (speedup 1.0000x reference)
#include <cuda_runtime.h>
#include <math.h>

#define KNN 20
#define NPTS 8192

// ---------------- scratch (device globals; no allocation allowed) ----------------
__device__ float g_feat[NPTS * 192];   // [x1 | x2 | x3] columns 0..191
__device__ float g_u[NPTS * 64];
__device__ float g_v[NPTS * 64];
__device__ float g_sq[NPTS];
__device__ int   g_idx[NPTS * KNN];
__device__ float g_h1[NPTS * 1024];
__device__ float g_h2[NPTS * 256];
__device__ float g_h3[NPTS * 128];

// ---------------- squared norms ----------------
__global__ void sqn_kernel(const float* __restrict__ X, int ldx, int C,
                           float* __restrict__ sq, int N)
{
    int i = blockIdx.x * blockDim.x + threadIdx.x;
    if (i < N) {
        float s = 0.f;
        for (int c = 0; c < C; c++) { float v = X[i * ldx + c]; s = fmaf(v, v, s); }
        sq[i] = s;
    }
}

// ---------------- fused kNN (distance + top-k selection) ----------------
// One warp per query row. x_i in registers; x_j tiles in shared (stride C+1).
// Per-lane top-20 (max-replace) in shared; warp-cooperative merge at the end.
template<int C, int TJ, int WARPS>
__global__ void knn_kernel(const float* __restrict__ X, int ldx,
                           const float* __restrict__ sqn,
                           int* __restrict__ idx, int N)
{
    extern __shared__ float sh[];
    float* sTile = sh;                              // TJ * (C+1)
    float* sSq   = sTile + TJ * (C + 1);            // TJ
    float* cd    = sSq + TJ;                        // WARPS*32*21
    int*   ci    = (int*)(cd + WARPS * 32 * 21);    // WARPS*32*21

    const int warpId = threadIdx.x >> 5;
    const int lane   = threadIdx.x & 31;
    const int row    = blockIdx.x * WARPS + warpId;

    float xi[C];
    #pragma unroll
    for (int c = 0; c < C; c++) xi[c] = X[row * ldx + c];

    float* myd = cd + (warpId * 32 + lane) * 21;
    int*   myi = ci + (warpId * 32 + lane) * 21;
    #pragma unroll
    for (int t = 0; t < KNN; t++) { myd[t] = INFINITY; myi[t] = 0x7fffffff; }
    float worst = INFINITY;
    int worstpos = 0;

    for (int base = 0; base < N; base += TJ) {
        __syncthreads();
        for (int t = threadIdx.x; t < TJ * C; t += blockDim.x) {
            int jj = t / C, c = t - jj * C;
            sTile[jj * (C + 1) + c] = X[(base + jj) * ldx + c];
        }
        for (int t = threadIdx.x; t < TJ; t += blockDim.x)
            sSq[t] = sqn[base + t];
        __syncthreads();

        #pragma unroll
        for (int q = 0; q < TJ / 32; q++) {
            int jj = q * 32 + lane;
            int j  = base + jj;
            const float* xr = sTile + jj * (C + 1);
            float acc = 0.f;
            #pragma unroll
            for (int c = 0; c < C; c++) acc = fmaf(xi[c], xr[c], acc);
            float d = sSq[jj] - 2.f * acc;   // ||xj||^2 - 2 xi.xj  (rank-equivalent)
            if (j != row && d < worst) {
                myd[worstpos] = d; myi[worstpos] = j;
                worst = -INFINITY;
                #pragma unroll
                for (int t = 0; t < KNN; t++) {
                    float v = myd[t];
                    if (v > worst) { worst = v; worstpos = t; }
                }
            }
        }
    }

    __syncwarp();
    // merge: 20 rounds of warp-wide (value, index) lexicographic min
    for (int r = 0; r < KNN; r++) {
        float bv = INFINITY; int bj = 0x7fffffff, bp = 0, bl = lane;
        #pragma unroll
        for (int t = 0; t < KNN; t++) {
            float v = myd[t];
            int   jv = myi[t];
            if (v < bv || (v == bv && jv < bj)) { bv = v; bj = jv; bp = t; }
        }
        #pragma unroll
        for (int off = 16; off; off >>= 1) {
            float ov = __shfl_xor_sync(~0u, bv, off);
            int   oj = __shfl_xor_sync(~0u, bj, off);
            int   ol = __shfl_xor_sync(~0u, bl, off);
            int   op = __shfl_xor_sync(~0u, bp, off);
            if (ov < bv || (ov == bv && oj < bj)) { bv = ov; bj = oj; bl = ol; bp = op; }
        }
        if (lane == bl) myd[bp] = INFINITY;
        if (lane == 0)  idx[row * KNN + r] = bj;
        __syncwarp();
    }
}

// ---------------- EdgeConv U/V GEMMs ----------------
// U = X @ (W_top - W_bot)  (stored as utop - v),  V = X @ W_bot. F = 64.
template<int C>
__global__ void uv_kernel(const float* __restrict__ X, int ldx,
                          const float* __restrict__ w,   // [2C, 64]
                          float* __restrict__ U, float* __restrict__ V, int N)
{
    __shared__ float sw[2 * C * 64];
    __shared__ float sx[4][C > 0 ? C : 1];
    int tid = threadIdx.y * 64 + threadIdx.x;
    for (int t = tid; t < 2 * C * 64; t += 256) sw[t] = w[t];
    int i = blockIdx.x * 4 + threadIdx.y;
    for (int c = threadIdx.x; c < C; c += 64) sx[threadIdx.y][c] = X[i * ldx + c];
    __syncthreads();

    int f = threadIdx.x;
    float u = 0.f, v = 0.f;
    #pragma unroll
    for (int c = 0; c < C; c++) {
        float xc = sx[threadIdx.y][c];
        u = fmaf(xc, sw[c * 64 + f], u);           // x . W_top
        v = fmaf(xc, sw[(C + c) * 64 + f], v);     // x . W_bot
    }
    U[i * 64 + f] = u - v;
    V[i * 64 + f] = v;
}

// ---------------- neighbor gather-max + relu ----------------
__global__ void edge_max_kernel(const float* __restrict__ U, const float* __restrict__ V,
                                const float* __restrict__ b, const int* __restrict__ idx,
                                float* __restrict__ out, int ldo, int colofs, int N)
{
    __shared__ int sidx[4][KNN];
    int i = blockIdx.x * 4 + threadIdx.y;
    if (threadIdx.x < KNN) sidx[threadIdx.y][threadIdx.x] = idx[i * KNN + threadIdx.x];
    __syncthreads();

    int f = threadIdx.x;
    float m = -INFINITY;
    #pragma unroll
    for (int t = 0; t < KNN; t++) {
        int j = sidx[threadIdx.y][t];
        m = fmaxf(m, V[j * 64 + f]);
    }
    float val = U[i * 64 + f] + b[f] + m;
    out[i * ldo + colofs + f] = fmaxf(val, 0.f);   // relu(max) == max(relu)
}

// ---------------- tiled SGEMM with fused bias (+relu) ----------------
// C[M,Nc] = act(A[M,K] @ B[K,Nc] + bias).  BM=BN=64, BK=16, 256 thr, 4x4/thread.
__global__ void sgemm_bias_relu(const float* __restrict__ A, int lda,
                                const float* __restrict__ B, int ldb,
                                const float* __restrict__ bias,
                                float* __restrict__ Cm, int ldc,
                                int Kdim, int relu)
{
    __shared__ float As[16][68];
    __shared__ float Bs[16][64];
    const int tid = threadIdx.x;
    const int tx = tid & 15, ty = tid >> 4;
    const int rowBase = blockIdx.y * 64;
    const int colBase = blockIdx.x * 64;

    const int ar = tid >> 2, akq = (tid & 3) * 4;    // A loader: 64 rows x 16 k
    const int bk = tid >> 4, bc = (tid & 15) * 4;    // B loader: 16 k x 64 cols

    float acc[4][4] = {};
    for (int k0 = 0; k0 < Kdim; k0 += 16) {
        float4 av = *(const float4*)&A[(rowBase + ar) * lda + k0 + akq];
        float4 bv = *(const float4*)&B[(k0 + bk) * ldb + colBase + bc];
        __syncthreads();
        As[akq + 0][ar] = av.x; As[akq + 1][ar] = av.y;
        As[akq + 2][ar] = av.z; As[akq + 3][ar] = av.w;
        *(float4*)&Bs[bk][bc] = bv;
        __syncthreads();
        #pragma unroll
        for (int kk = 0; kk < 16; kk++) {
            float a[4], bb[4];
            #pragma unroll
            for (int m = 0; m < 4; m++) a[m] = As[kk][ty * 4 + m];
            #pragma unroll
            for (int n = 0; n < 4; n++) bb[n] = Bs[kk][tx * 4 + n];
            #pragma unroll
            for (int m = 0; m < 4; m++)
                #pragma unroll
                for (int n = 0; n < 4; n++)
                    acc[m][n] = fmaf(a[m], bb[n], acc[m][n]);
        }
    }
    #pragma unroll
    for (int m = 0; m < 4; m++) {
        int r = rowBase + ty * 4 + m;
        #pragma unroll
        for (int n = 0; n < 4; n++) {
            int c = colBase + tx * 4 + n;
            float v = acc[m][n] + bias[c];
            if (relu) v = fmaxf(v, 0.f);
            Cm[r * ldc + c] = v;
        }
    }
}

// ---------------- final 128->13 + log_softmax (one warp per row) ----------------
__global__ void final_logsoftmax(const float* __restrict__ H,
                                 const float* __restrict__ W,  // [128,13]
                                 const float* __restrict__ b,
                                 float* __restrict__ out, int N)
{
    __shared__ float sw[128 * 13];
    __shared__ float sb[13];
    int tid = threadIdx.x;
    for (int t = tid; t < 128 * 13; t += 256) sw[t] = W[t];
    if (tid < 13) sb[tid] = b[tid];
    __syncthreads();

    int warp = tid >> 5, lane = tid & 31;
    int i = blockIdx.x * 8 + warp;

    float h[4];
    #pragma unroll
    for (int q = 0; q < 4; q++) h[q] = H[i * 128 + q * 32 + lane];

    float z[13];
    #pragma unroll
    for (int f = 0; f < 13; f++) {
        float acc = 0.f;
        #pragma unroll
        for (int q = 0; q < 4; q++)
            acc = fmaf(h[q], sw[(q * 32 + lane) * 13 + f], acc);
        #pragma unroll
        for (int off = 16; off; off >>= 1)
            acc += __shfl_xor_sync(~0u, acc, off);
        z[f] = acc + sb[f];
    }
    float m = z[0];
    #pragma unroll
    for (int f = 1; f < 13; f++) m = fmaxf(m, z[f]);
    float s = 0.f;
    #pragma unroll
    for (int f = 0; f < 13; f++) s += expf(z[f] - m);
    float lse = m + logf(s);
    if (lane == 0) {
        #pragma unroll
        for (int f = 0; f < 13; f++) out[i * 13 + f] = z[f] - lse;
    }
}

// ---------------- launch ----------------
extern "C" void kernel_launch(void* const* d_in, const int* in_sizes, int n_in,
                              void* d_out, int out_size)
{
    const float* x   = (const float*)d_in[0];
    const float* w1  = (const float*)d_in[1];
    const float* b1  = (const float*)d_in[2];
    const float* w2  = (const float*)d_in[3];
    const float* b2  = (const float*)d_in[4];
    const float* w3  = (const float*)d_in[5];
    const float* b3  = (const float*)d_in[6];
    const float* wl1 = (const float*)d_in[7];
    const float* bl1 = (const float*)d_in[8];
    const float* wm1 = (const float*)d_in[9];
    const float* bm1 = (const float*)d_in[10];
    const float* wm2 = (const float*)d_in[11];
    const float* bm2 = (const float*)d_in[12];
    const float* wm3 = (const float*)d_in[13];
    const float* bm3 = (const float*)d_in[14];
    float* out = (float*)d_out;
    const int N = NPTS;

    float *feat, *u, *v, *sq, *h1, *h2, *h3; int* idx;
    cudaGetSymbolAddress((void**)&feat, g_feat);
    cudaGetSymbolAddress((void**)&u,    g_u);
    cudaGetSymbolAddress((void**)&v,    g_v);
    cudaGetSymbolAddress((void**)&sq,   g_sq);
    cudaGetSymbolAddress((void**)&idx,  g_idx);
    cudaGetSymbolAddress((void**)&h1,   g_h1);
    cudaGetSymbolAddress((void**)&h2,   g_h2);
    cudaGetSymbolAddress((void**)&h3,   g_h3);

    const size_t sh3  = 128 * 4  * 4 + 128 * 4 + 8 * 32 * 21 * 8;   // 45.5 KB
    const size_t sh64 = 128 * 65 * 4 + 128 * 4 + 8 * 32 * 21 * 8;   // 76.8 KB
    cudaFuncSetAttribute((const void*)knn_kernel<64, 128, 8>,
                         cudaFuncAttributeMaxDynamicSharedMemorySize, (int)sh64);

    dim3 b64x4(64, 4);

    // ---- layer 1 (C=3) ----
    sqn_kernel<<<N / 256, 256>>>(x, 3, 3, sq, N);
    knn_kernel<3, 128, 8><<<N / 8, 256, sh3>>>(x, 3, sq, idx, N);
    uv_kernel<3><<<N / 4, b64x4>>>(x, 3, w1, u, v, N);
    edge_max_kernel<<<N / 4, b64x4>>>(u, v, b1, idx, feat, 192, 0, N);

    // ---- layer 2 (C=64 on x1 = feat[:,0:64]) ----
    sqn_kernel<<<N / 256, 256>>>(feat, 192, 64, sq, N);
    knn_kernel<64, 128, 8><<<N / 8, 256, sh64>>>(feat, 192, sq, idx, N);
    uv_kernel<64><<<N / 4, b64x4>>>(feat, 192, w2, u, v, N);
    edge_max_kernel<<<N / 4, b64x4>>>(u, v, b2, idx, feat, 192, 64, N);

    // ---- layer 3 (C=64 on x2 = feat[:,64:128]) ----
    sqn_kernel<<<N / 256, 256>>>(feat + 64, 192, 64, sq, N);
    knn_kernel<64, 128, 8><<<N / 8, 256, sh64>>>(feat + 64, 192, sq, idx, N);
    uv_kernel<64><<<N / 4, b64x4>>>(feat + 64, 192, w3, u, v, N);
    edge_max_kernel<<<N / 4, b64x4>>>(u, v, b3, idx, feat, 192, 128, N);

    // ---- MLP head ----
    sgemm_bias_relu<<<dim3(16, 128), 256>>>(feat, 192, wl1, 1024, bl1, h1, 1024, 192, 1);
    sgemm_bias_relu<<<dim3(4, 128), 256>>>(h1, 1024, wm1, 256, bm1, h2, 256, 1024, 1);
    sgemm_bias_relu<<<dim3(2, 128), 256>>>(h2, 256, wm2, 128, bm2, h3, 128, 256, 1);
    final_logsoftmax<<<N / 8, 256>>>(h3, wm3, bm3, out, N);
}

// round 2
// speedup vs baseline: 1.8793x; 1.8793x over previous
#include <cuda_runtime.h>
#include <math.h>

#define KNN 20
#define NPTS 8192
typedef unsigned long long ull;

// ---------------- scratch ----------------
__device__ float g_feat[NPTS * 192];
__device__ float g_u[NPTS * 64];
__device__ float g_v[NPTS * 64];
__device__ float g_sq[NPTS];
__device__ int   g_idx[NPTS * KNN];
__device__ float g_h1[NPTS * 1024];
__device__ float g_h2[NPTS * 256];
__device__ float g_h3[NPTS * 128];

__device__ __forceinline__ void fma2(ull& d, ull a, ull b) {
    asm("fma.rn.f32x2 %0, %1, %2, %0;" : "+l"(d) : "l"(a), "l"(b));
}
__device__ __forceinline__ float sum2(ull u) {
    return __uint_as_float((unsigned)u) + __uint_as_float((unsigned)(u >> 32));
}

// ---------------- squared norms ----------------
__global__ void sqn_kernel(const float* __restrict__ X, int ldx, int C,
                           float* __restrict__ sq, int N)
{
    int i = blockIdx.x * blockDim.x + threadIdx.x;
    if (i < N) {
        float s = 0.f;
        for (int c = 0; c < C; c++) { float v = X[i * ldx + c]; s = fmaf(v, v, s); }
        sq[i] = s;
    }
}

// ---------------- legacy small-dim kNN (C=3, layer 1) ----------------
template<int C, int TJ, int WARPS>
__global__ void knn_kernel(const float* __restrict__ X, int ldx,
                           const float* __restrict__ sqn,
                           int* __restrict__ idx, int N)
{
    extern __shared__ float sh[];
    float* sTile = sh;
    float* sSq   = sTile + TJ * (C + 1);
    float* cd    = sSq + TJ;
    int*   ci    = (int*)(cd + WARPS * 32 * 21);

    const int warpId = threadIdx.x >> 5;
    const int lane   = threadIdx.x & 31;
    const int row    = blockIdx.x * WARPS + warpId;

    float xi[C];
    #pragma unroll
    for (int c = 0; c < C; c++) xi[c] = X[row * ldx + c];

    float* myd = cd + (warpId * 32 + lane) * 21;
    int*   myi = ci + (warpId * 32 + lane) * 21;
    #pragma unroll
    for (int t = 0; t < KNN; t++) { myd[t] = INFINITY; myi[t] = 0x7fffffff; }
    float worst = INFINITY;
    int worstpos = 0;

    for (int base = 0; base < N; base += TJ) {
        __syncthreads();
        for (int t = threadIdx.x; t < TJ * C; t += blockDim.x) {
            int jj = t / C, c = t - jj * C;
            sTile[jj * (C + 1) + c] = X[(base + jj) * ldx + c];
        }
        for (int t = threadIdx.x; t < TJ; t += blockDim.x)
            sSq[t] = sqn[base + t];
        __syncthreads();

        #pragma unroll
        for (int q = 0; q < TJ / 32; q++) {
            int jj = q * 32 + lane;
            int j  = base + jj;
            const float* xr = sTile + jj * (C + 1);
            float acc = 0.f;
            #pragma unroll
            for (int c = 0; c < C; c++) acc = fmaf(xi[c], xr[c], acc);
            float d = sSq[jj] - 2.f * acc;
            if (j != row && d < worst) {
                myd[worstpos] = d; myi[worstpos] = j;
                worst = -INFINITY;
                #pragma unroll
                for (int t = 0; t < KNN; t++) {
                    float v = myd[t];
                    if (v > worst) { worst = v; worstpos = t; }
                }
            }
        }
    }

    __syncwarp();
    for (int r = 0; r < KNN; r++) {
        float bv = INFINITY; int bj = 0x7fffffff, bp = 0, bl = lane;
        #pragma unroll
        for (int t = 0; t < KNN; t++) {
            float v = myd[t]; int jv = myi[t];
            if (v < bv || (v == bv && jv < bj)) { bv = v; bj = jv; bp = t; }
        }
        #pragma unroll
        for (int off = 16; off; off >>= 1) {
            float ov = __shfl_xor_sync(~0u, bv, off);
            int   oj = __shfl_xor_sync(~0u, bj, off);
            int   ol = __shfl_xor_sync(~0u, bl, off);
            int   op = __shfl_xor_sync(~0u, bp, off);
            if (ov < bv || (ov == bv && oj < bj)) { bv = ov; bj = oj; bl = ol; bp = op; }
        }
        if (lane == bl) myd[bp] = INFINITY;
        if (lane == 0)  idx[row * KNN + r] = bj;
        __syncwarp();
    }
}

// ---------------- fast kNN for C=64: f32x2 GEMM-tiled + register top-k ----------------
// Block: 256 thr (8 warps). 64 query rows/block, 256-candidate tiles.
// GEMM: 8x8 micro-tile per thread in packed f32x2 over 32 k-pairs.
// Selection: warp w owns rows w*8..w*8+7; lanes 0..19 hold the top-20 entries.
__global__ void __launch_bounds__(256, 1)
knn64_kernel(const float* __restrict__ X, int ldx,
             const float* __restrict__ sqn,
             int* __restrict__ idx, int N)
{
    extern __shared__ float sh[];
    float2* Qs2   = (float2*)sh;               // [32][64]   16KB
    float2* Cs2   = Qs2 + 32 * 64;             // [32][256]  64KB
    float*  sDist = (float*)(Cs2 + 32 * 256);  // [64][256]  64KB
    float*  sSq   = sDist + 64 * 256;          // [256]       1KB

    const int tid  = threadIdx.x;
    const int ty   = tid >> 5;     // warp id, row group
    const int tx   = tid & 31;     // lane, col group
    const int rowBase = blockIdx.x * 64;

    // --- load Q tile (64 rows x 64 dims), packed as k-pairs ---
    {
        int r  = tid >> 2;
        int cq = (tid & 3) * 16;
        const float* xr = X + (rowBase + r) * ldx + cq;
        #pragma unroll
        for (int q = 0; q < 4; q++) {
            float4 v = *(const float4*)(xr + q * 4);
            int kp = (cq >> 1) + q * 2;
            Qs2[(kp + 0) * 64 + r] = make_float2(v.x, v.y);
            Qs2[(kp + 1) * 64 + r] = make_float2(v.z, v.w);
        }
    }

    // --- per-row top-k state (warp ty owns rows ty*8..ty*8+7) ---
    float bestd[8], wv[8];
    int   bestj[8];
    #pragma unroll
    for (int rr = 0; rr < 8; rr++) {
        bestd[rr] = (tx < KNN) ? INFINITY : -INFINITY;
        bestj[rr] = 0x7fffffff;
        wv[rr]    = INFINITY;
    }

    for (int base = 0; base < N; base += 256) {
        // --- load candidate tile: 1 row per thread, pack k-pairs ---
        {
            const float* xr = X + (base + tid) * ldx;
            #pragma unroll
            for (int q = 0; q < 16; q++) {
                float4 v = *(const float4*)(xr + q * 4);
                Cs2[(2 * q + 0) * 256 + tid] = make_float2(v.x, v.y);
                Cs2[(2 * q + 1) * 256 + tid] = make_float2(v.z, v.w);
            }
            sSq[tid] = sqn[base + tid];
        }
        __syncthreads();

        // --- GEMM: acc[m][n] over 32 k-pairs ---
        ull acc[8][8];
        #pragma unroll
        for (int m = 0; m < 8; m++)
            #pragma unroll
            for (int n = 0; n < 8; n++) acc[m][n] = 0ull;

        #pragma unroll 4
        for (int kp = 0; kp < 32; kp++) {
            ull a[8], b[8];
            const ulonglong2* pa0 = (const ulonglong2*)(Qs2 + kp * 64 + ty * 4);
            const ulonglong2* pa1 = (const ulonglong2*)(Qs2 + kp * 64 + 32 + ty * 4);
            ulonglong2 A0 = pa0[0], A1 = pa0[1], A2 = pa1[0], A3 = pa1[1];
            a[0] = A0.x; a[1] = A0.y; a[2] = A1.x; a[3] = A1.y;
            a[4] = A2.x; a[5] = A2.y; a[6] = A3.x; a[7] = A3.y;
            #pragma unroll
            for (int ch = 0; ch < 4; ch++) {
                ulonglong2 B = *(const ulonglong2*)(Cs2 + kp * 256 + ch * 64 + tx * 2);
                b[2 * ch] = B.x; b[2 * ch + 1] = B.y;
            }
            #pragma unroll
            for (int m = 0; m < 8; m++)
                #pragma unroll
                for (int n = 0; n < 8; n++)
                    fma2(acc[m][n], a[m], b[n]);
        }

        // --- epilogue: dist = ||xj||^2 - 2 xi.xj -> shared tile ---
        #pragma unroll
        for (int m = 0; m < 8; m++) {
            int row = (m < 4) ? (ty * 4 + m) : (32 + ty * 4 + (m - 4));
            #pragma unroll
            for (int ch = 0; ch < 4; ch++) {
                int col = ch * 64 + tx * 2;
                float d0 = sSq[col]     - 2.f * sum2(acc[m][2 * ch]);
                float d1 = sSq[col + 1] - 2.f * sum2(acc[m][2 * ch + 1]);
                *(float2*)&sDist[row * 256 + col] = make_float2(d0, d1);
            }
        }
        __syncthreads();

        // --- selection: warp ty scans rows ty*8..+7, 256 candidates ---
        #pragma unroll
        for (int rr = 0; rr < 8; rr++) {
            int row  = ty * 8 + rr;
            int grow = rowBase + row;
            #pragma unroll
            for (int q = 0; q < 8; q++) {
                int   cand = q * 32 + tx;
                int   j    = base + cand;
                float d    = sDist[row * 256 + cand];
                bool pass  = (d < wv[rr]) && (j != grow);
                unsigned mask = __ballot_sync(~0u, pass);
                while (mask) {
                    int src = __ffs(mask) - 1; mask &= mask - 1;
                    float dd = __shfl_sync(~0u, d, src);
                    int   jj = base + q * 32 + src;
                    if (dd >= wv[rr]) continue;
                    // warp argmax over entries (tie: evict larger index)
                    float v = bestd[rr]; int jv = bestj[rr], ln = tx;
                    #pragma unroll
                    for (int off = 16; off; off >>= 1) {
                        float ov = __shfl_xor_sync(~0u, v, off);
                        int   oj = __shfl_xor_sync(~0u, jv, off);
                        int   ol = __shfl_xor_sync(~0u, ln, off);
                        if (ov > v || (ov == v && oj > jv)) { v = ov; jv = oj; ln = ol; }
                    }
                    if (tx == ln) { bestd[rr] = dd; bestj[rr] = jj; }
                    float v2 = bestd[rr];
                    #pragma unroll
                    for (int off = 16; off; off >>= 1)
                        v2 = fmaxf(v2, __shfl_xor_sync(~0u, v2, off));
                    wv[rr] = v2;
                }
            }
        }
        __syncthreads();
    }

    #pragma unroll
    for (int rr = 0; rr < 8; rr++) {
        if (tx < KNN)
            idx[(rowBase + ty * 8 + rr) * KNN + tx] = bestj[rr];
    }
}

// ---------------- EdgeConv U/V ----------------
template<int C>
__global__ void uv_kernel(const float* __restrict__ X, int ldx,
                          const float* __restrict__ w,
                          float* __restrict__ U, float* __restrict__ V, int N)
{
    __shared__ float sw[2 * C * 64];
    __shared__ float sx[4][C > 0 ? C : 1];
    int tid = threadIdx.y * 64 + threadIdx.x;
    for (int t = tid; t < 2 * C * 64; t += 256) sw[t] = w[t];
    int i = blockIdx.x * 4 + threadIdx.y;
    for (int c = threadIdx.x; c < C; c += 64) sx[threadIdx.y][c] = X[i * ldx + c];
    __syncthreads();

    int f = threadIdx.x;
    float u = 0.f, v = 0.f;
    #pragma unroll
    for (int c = 0; c < C; c++) {
        float xc = sx[threadIdx.y][c];
        u = fmaf(xc, sw[c * 64 + f], u);
        v = fmaf(xc, sw[(C + c) * 64 + f], v);
    }
    U[i * 64 + f] = u - v;
    V[i * 64 + f] = v;
}

// ---------------- neighbor gather-max + relu ----------------
__global__ void edge_max_kernel(const float* __restrict__ U, const float* __restrict__ V,
                                const float* __restrict__ b, const int* __restrict__ idx,
                                float* __restrict__ out, int ldo, int colofs, int N)
{
    __shared__ int sidx[4][KNN];
    int i = blockIdx.x * 4 + threadIdx.y;
    if (threadIdx.x < KNN) sidx[threadIdx.y][threadIdx.x] = idx[i * KNN + threadIdx.x];
    __syncthreads();

    int f = threadIdx.x;
    float m = -INFINITY;
    #pragma unroll
    for (int t = 0; t < KNN; t++) {
        int j = sidx[threadIdx.y][t];
        m = fmaxf(m, V[j * 64 + f]);
    }
    float val = U[i * 64 + f] + b[f] + m;
    out[i * ldo + colofs + f] = fmaxf(val, 0.f);
}

// ---------------- f32x2 SGEMM 64x256, fused bias+relu ----------------
// grid.x = col blocks (N/256), grid.y = row blocks (M/64). K % 32 == 0.
__global__ void __launch_bounds__(256, 1)
gemm_f2_64x256(const float* __restrict__ A, int lda,
               const float* __restrict__ B, int ldb,
               const float* __restrict__ bias,
               float* __restrict__ C, int ldc, int K)
{
    __shared__ float2 As2[16][64];    // 8KB
    __shared__ float2 Bs2[16][256];   // 32KB

    const int tid = threadIdx.x;
    const int ty  = tid >> 5, tx = tid & 31;
    const int rowBase = blockIdx.y * 64;
    const int colBase = blockIdx.x * 256;

    ull acc[8][8];
    #pragma unroll
    for (int m = 0; m < 8; m++)
        #pragma unroll
        for (int n = 0; n < 8; n++) acc[m][n] = 0ull;

    const int ar = tid >> 2, ac = (tid & 3) * 8;   // A loader
    const int bkp = tid >> 4, bc0 = (tid & 15) * 4; // B loader

    for (int k0 = 0; k0 < K; k0 += 32) {
        float4 v0 = *(const float4*)&A[(rowBase + ar) * lda + k0 + ac];
        float4 v1 = *(const float4*)&A[(rowBase + ar) * lda + k0 + ac + 4];
        float4 blo[4], bhi[4];
        #pragma unroll
        for (int rep = 0; rep < 4; rep++) {
            int col = colBase + rep * 64 + bc0;
            blo[rep] = *(const float4*)&B[(k0 + 2 * bkp) * ldb + col];
            bhi[rep] = *(const float4*)&B[(k0 + 2 * bkp + 1) * ldb + col];
        }
        __syncthreads();
        As2[(ac >> 1) + 0][ar] = make_float2(v0.x, v0.y);
        As2[(ac >> 1) + 1][ar] = make_float2(v0.z, v0.w);
        As2[(ac >> 1) + 2][ar] = make_float2(v1.x, v1.y);
        As2[(ac >> 1) + 3][ar] = make_float2(v1.z, v1.w);
        #pragma unroll
        for (int rep = 0; rep < 4; rep++) {
            int c = rep * 64 + bc0;
            Bs2[bkp][c + 0] = make_float2(blo[rep].x, bhi[rep].x);
            Bs2[bkp][c + 1] = make_float2(blo[rep].y, bhi[rep].y);
            Bs2[bkp][c + 2] = make_float2(blo[rep].z, bhi[rep].z);
            Bs2[bkp][c + 3] = make_float2(blo[rep].w, bhi[rep].w);
        }
        __syncthreads();

        #pragma unroll 4
        for (int kp = 0; kp < 16; kp++) {
            ull a[8], b[8];
            const ulonglong2* pa0 = (const ulonglong2*)(&As2[kp][ty * 4]);
            const ulonglong2* pa1 = (const ulonglong2*)(&As2[kp][32 + ty * 4]);
            ulonglong2 A0 = pa0[0], A1 = pa0[1], A2 = pa1[0], A3 = pa1[1];
            a[0] = A0.x; a[1] = A0.y; a[2] = A1.x; a[3] = A1.y;
            a[4] = A2.x; a[5] = A2.y; a[6] = A3.x; a[7] = A3.y;
            #pragma unroll
            for (int ch = 0; ch < 4; ch++) {
                ulonglong2 Bv = *(const ulonglong2*)(&Bs2[kp][ch * 64 + tx * 2]);
                b[2 * ch] = Bv.x; b[2 * ch + 1] = Bv.y;
            }
            #pragma unroll
            for (int m = 0; m < 8; m++)
                #pragma unroll
                for (int n = 0; n < 8; n++)
                    fma2(acc[m][n], a[m], b[n]);
        }
    }

    #pragma unroll
    for (int m = 0; m < 8; m++) {
        int row = rowBase + ((m < 4) ? (ty * 4 + m) : (32 + ty * 4 + (m - 4)));
        #pragma unroll
        for (int ch = 0; ch < 4; ch++) {
            int col = colBase + ch * 64 + tx * 2;
            float d0 = fmaxf(sum2(acc[m][2 * ch])     + bias[col],     0.f);
            float d1 = fmaxf(sum2(acc[m][2 * ch + 1]) + bias[col + 1], 0.f);
            *(float2*)&C[row * ldc + col] = make_float2(d0, d1);
        }
    }
}

// ---------------- small SGEMM (wm2) ----------------
__global__ void sgemm_bias_relu(const float* __restrict__ A, int lda,
                                const float* __restrict__ B, int ldb,
                                const float* __restrict__ bias,
                                float* __restrict__ Cm, int ldc,
                                int Kdim, int relu)
{
    __shared__ float As[16][68];
    __shared__ float Bs[16][64];
    const int tid = threadIdx.x;
    const int tx = tid & 15, ty = tid >> 4;
    const int rowBase = blockIdx.y * 64;
    const int colBase = blockIdx.x * 64;

    const int ar = tid >> 2, akq = (tid & 3) * 4;
    const int bk = tid >> 4, bc = (tid & 15) * 4;

    float acc[4][4] = {};
    for (int k0 = 0; k0 < Kdim; k0 += 16) {
        float4 av = *(const float4*)&A[(rowBase + ar) * lda + k0 + akq];
        float4 bv = *(const float4*)&B[(k0 + bk) * ldb + colBase + bc];
        __syncthreads();
        As[akq + 0][ar] = av.x; As[akq + 1][ar] = av.y;
        As[akq + 2][ar] = av.z; As[akq + 3][ar] = av.w;
        *(float4*)&Bs[bk][bc] = bv;
        __syncthreads();
        #pragma unroll
        for (int kk = 0; kk < 16; kk++) {
            float a[4], bb[4];
            #pragma unroll
            for (int m = 0; m < 4; m++) a[m] = As[kk][ty * 4 + m];
            #pragma unroll
            for (int n = 0; n < 4; n++) bb[n] = Bs[kk][tx * 4 + n];
            #pragma unroll
            for (int m = 0; m < 4; m++)
                #pragma unroll
                for (int n = 0; n < 4; n++)
                    acc[m][n] = fmaf(a[m], bb[n], acc[m][n]);
        }
    }
    #pragma unroll
    for (int m = 0; m < 4; m++) {
        int r = rowBase + ty * 4 + m;
        #pragma unroll
        for (int n = 0; n < 4; n++) {
            int c = colBase + tx * 4 + n;
            float v = acc[m][n] + bias[c];
            if (relu) v = fmaxf(v, 0.f);
            Cm[r * ldc + c] = v;
        }
    }
}

// ---------------- final 128->13 + log_softmax ----------------
__global__ void final_logsoftmax(const float* __restrict__ H,
                                 const float* __restrict__ W,
                                 const float* __restrict__ b,
                                 float* __restrict__ out, int N)
{
    __shared__ float sw[128 * 13];
    __shared__ float sb[13];
    int tid = threadIdx.x;
    for (int t = tid; t < 128 * 13; t += 256) sw[t] = W[t];
    if (tid < 13) sb[tid] = b[tid];
    __syncthreads();

    int warp = tid >> 5, lane = tid & 31;
    int i = blockIdx.x * 8 + warp;

    float h[4];
    #pragma unroll
    for (int q = 0; q < 4; q++) h[q] = H[i * 128 + q * 32 + lane];

    float z[13];
    #pragma unroll
    for (int f = 0; f < 13; f++) {
        float acc = 0.f;
        #pragma unroll
        for (int q = 0; q < 4; q++)
            acc = fmaf(h[q], sw[(q * 32 + lane) * 13 + f], acc);
        #pragma unroll
        for (int off = 16; off; off >>= 1)
            acc += __shfl_xor_sync(~0u, acc, off);
        z[f] = acc + sb[f];
    }
    float m = z[0];
    #pragma unroll
    for (int f = 1; f < 13; f++) m = fmaxf(m, z[f]);
    float s = 0.f;
    #pragma unroll
    for (int f = 0; f < 13; f++) s += expf(z[f] - m);
    float lse = m + logf(s);
    if (lane == 0) {
        #pragma unroll
        for (int f = 0; f < 13; f++) out[i * 13 + f] = z[f] - lse;
    }
}

// ---------------- launch ----------------
extern "C" void kernel_launch(void* const* d_in, const int* in_sizes, int n_in,
                              void* d_out, int out_size)
{
    const float* x   = (const float*)d_in[0];
    const float* w1  = (const float*)d_in[1];
    const float* b1  = (const float*)d_in[2];
    const float* w2  = (const float*)d_in[3];
    const float* b2  = (const float*)d_in[4];
    const float* w3  = (const float*)d_in[5];
    const float* b3  = (const float*)d_in[6];
    const float* wl1 = (const float*)d_in[7];
    const float* bl1 = (const float*)d_in[8];
    const float* wm1 = (const float*)d_in[9];
    const float* bm1 = (const float*)d_in[10];
    const float* wm2 = (const float*)d_in[11];
    const float* bm2 = (const float*)d_in[12];
    const float* wm3 = (const float*)d_in[13];
    const float* bm3 = (const float*)d_in[14];
    float* out = (float*)d_out;
    const int N = NPTS;

    float *feat, *u, *v, *sq, *h1, *h2, *h3; int* idx;
    cudaGetSymbolAddress((void**)&feat, g_feat);
    cudaGetSymbolAddress((void**)&u,    g_u);
    cudaGetSymbolAddress((void**)&v,    g_v);
    cudaGetSymbolAddress((void**)&sq,   g_sq);
    cudaGetSymbolAddress((void**)&idx,  g_idx);
    cudaGetSymbolAddress((void**)&h1,   g_h1);
    cudaGetSymbolAddress((void**)&h2,   g_h2);
    cudaGetSymbolAddress((void**)&h3,   g_h3);

    const size_t sh3   = 128 * 4 * 4 + 128 * 4 + 8 * 32 * 21 * 8;
    const size_t shK64 = 32 * 64 * 8 + 32 * 256 * 8 + 64 * 256 * 4 + 256 * 4; // 148480
    cudaFuncSetAttribute((const void*)knn64_kernel,
                         cudaFuncAttributeMaxDynamicSharedMemorySize, (int)shK64);

    dim3 b64x4(64, 4);

    // ---- layer 1 (C=3) ----
    sqn_kernel<<<N / 256, 256>>>(x, 3, 3, sq, N);
    knn_kernel<3, 128, 8><<<N / 8, 256, sh3>>>(x, 3, sq, idx, N);
    uv_kernel<3><<<N / 4, b64x4>>>(x, 3, w1, u, v, N);
    edge_max_kernel<<<N / 4, b64x4>>>(u, v, b1, idx, feat, 192, 0, N);

    // ---- layer 2 (C=64 on feat[:,0:64]) ----
    sqn_kernel<<<N / 256, 256>>>(feat, 192, 64, sq, N);
    knn64_kernel<<<N / 64, 256, shK64>>>(feat, 192, sq, idx, N);
    uv_kernel<64><<<N / 4, b64x4>>>(feat, 192, w2, u, v, N);
    edge_max_kernel<<<N / 4, b64x4>>>(u, v, b2, idx, feat, 192, 64, N);

    // ---- layer 3 (C=64 on feat[:,64:128]) ----
    sqn_kernel<<<N / 256, 256>>>(feat + 64, 192, 64, sq, N);
    knn64_kernel<<<N / 64, 256, shK64>>>(feat + 64, 192, sq, idx, N);
    uv_kernel<64><<<N / 4, b64x4>>>(feat + 64, 192, w3, u, v, N);
    edge_max_kernel<<<N / 4, b64x4>>>(u, v, b3, idx, feat, 192, 128, N);

    // ---- MLP head ----
    gemm_f2_64x256<<<dim3(4, 128), 256>>>(feat, 192, wl1, 1024, bl1, h1, 1024, 192);
    gemm_f2_64x256<<<dim3(1, 128), 256>>>(h1, 1024, wm1, 256, bm1, h2, 256, 1024);
    sgemm_bias_relu<<<dim3(2, 128), 256>>>(h2, 256, wm2, 128, bm2, h3, 128, 256, 1);
    final_logsoftmax<<<N / 8, 256>>>(h3, wm3, bm3, out, N);
}